// round 5
// baseline (speedup 1.0000x reference)
#include <cuda_runtime.h>
#include <cstdint>

#define NQ 32
#define NS 25
#define NL 64
#define NF 256
#define NH 64

// Scratch (allocation-free rule: __device__ globals)
__device__ float g_WqT[NQ * NH * NL];       // per q: [h][i], prescaled by 2*log2e
__device__ float g_WhT[NS * NH * NL];       // per s: [h][j]
__device__ float g_att[NQ * NS * NL * NL];  // softmaxed attention [q][s][i][j]

typedef unsigned long long u64;

__device__ __forceinline__ float fast_ex2(float x) {
    float r; asm("ex2.approx.f32 %0, %1;" : "=f"(r) : "f"(x)); return r;
}
__device__ __forceinline__ float fast_rcp(float x) {
    float r; asm("rcp.approx.f32 %0, %1;" : "=f"(r) : "f"(x)); return r;
}
// ---- packed f32x2 ops ----
__device__ __forceinline__ u64 f2mul(u64 a, u64 b) {
    u64 r; asm("mul.rn.f32x2 %0, %1, %2;" : "=l"(r) : "l"(a), "l"(b)); return r;
}
__device__ __forceinline__ u64 f2fma(u64 a, u64 b, u64 c) {
    u64 r; asm("fma.rn.f32x2 %0, %1, %2, %3;" : "=l"(r) : "l"(a), "l"(b), "l"(c)); return r;
}
__device__ __forceinline__ u64 pk(float lo, float hi) {
    u64 r; asm("mov.b64 %0, {%1, %2};" : "=l"(r) : "f"(lo), "f"(hi)); return r;
}
__device__ __forceinline__ float2 upk(u64 v) {
    float lo, hi; asm("mov.b64 {%0, %1}, %2;" : "=f"(lo), "=f"(hi) : "l"(v));
    return make_float2(lo, hi);
}
__device__ __forceinline__ u64 dup2(float x) { return pk(x, x); }

// Degree-6 polynomial G(u) ~= (1-u)/(1+u) on [0,1], max abs err ~3.6e-5.
#define G0c 0.999956458f
#define G1c -1.996579368f
#define G2c 1.952699598f
#define G3c -1.733862064f
#define G4c 1.203783808f
#define G5c -0.533660512f
#define G6c 0.10766208f

#define TWO_LOG2E 2.8853900817779268f   // 2*log2(e)
#define LOG2E 1.4426950408889634f

// K1: projection (absorbs W transpose + 2*log2e prescale of Wq).
// Block b < NQ handles qs[b], else hs[b-NQ].
// dst[h][l] = (sum_f x[l][f] * W[h][f] + bias[h]) * scale, stored h-major.
#define WPAD 4
__global__ __launch_bounds__(256) void k_project(const float* __restrict__ qs,
                                                 const float* __restrict__ hs,
                                                 const float* __restrict__ W,
                                                 const float* __restrict__ bias) {
    extern __shared__ float sm[];
    float* xs = sm;                       // [NL][NF]
    float* wh = sm + NL * NF;             // [NH][NF+WPAD]
    const int b = blockIdx.x;
    const int t = threadIdx.x;
    const float* x = (b < NQ) ? (qs + (size_t)b * NL * NF)
                              : (hs + (size_t)(b - NQ) * NL * NF);
    float* dst = (b < NQ) ? (g_WqT + (size_t)b * NH * NL)
                          : (g_WhT + (size_t)(b - NQ) * NH * NL);
    const float scale = (b < NQ) ? TWO_LOG2E : 1.0f;

    {
        const float4* xg = reinterpret_cast<const float4*>(x);
        float4* xs4 = reinterpret_cast<float4*>(xs);
        for (int e = t; e < NL * NF / 4; e += 256) xs4[e] = xg[e];
        const float4* wg = reinterpret_cast<const float4*>(W);
        for (int e = t; e < NH * NF / 4; e += 256) {
            int h = e / (NF / 4);
            int f4 = e % (NF / 4);
            *reinterpret_cast<float4*>(&wh[h * (NF + WPAD) + 4 * f4]) = wg[e];
        }
    }
    __syncthreads();

    const int h0 = 4 * (t & 15);
    const int l0 = 4 * (t >> 4);
    float acc[4][4];
    #pragma unroll
    for (int c = 0; c < 4; c++)
        #pragma unroll
        for (int r = 0; r < 4; r++) acc[c][r] = 0.f;

    for (int f = 0; f < NF; f += 4) {
        float xv[4][4];
        #pragma unroll
        for (int r = 0; r < 4; r++) {
            float4 v = *reinterpret_cast<const float4*>(&xs[(l0 + r) * NF + f]);
            xv[r][0] = v.x; xv[r][1] = v.y; xv[r][2] = v.z; xv[r][3] = v.w;
        }
        #pragma unroll
        for (int c = 0; c < 4; c++) {
            float4 w = *reinterpret_cast<const float4*>(&wh[(h0 + c) * (NF + WPAD) + f]);
            float wv[4] = {w.x, w.y, w.z, w.w};
            #pragma unroll
            for (int i = 0; i < 4; i++)
                #pragma unroll
                for (int r = 0; r < 4; r++)
                    acc[c][r] = fmaf(wv[i], xv[r][i], acc[c][r]);
        }
    }
    #pragma unroll
    for (int c = 0; c < 4; c++) {
        float bb = __ldg(&bias[h0 + c]);
        float4 v = make_float4((acc[c][0] + bb) * scale, (acc[c][1] + bb) * scale,
                               (acc[c][2] + bb) * scale, (acc[c][3] + bb) * scale);
        *reinterpret_cast<float4*>(&dst[(h0 + c) * NL + l0]) = v;
    }
}

// K2: scores (tanh-sum) + softmax. One block per (q, s, i-half).
// Writes softmaxed att[q][s][i][j] to g_att.
__global__ __launch_bounds__(256) void k_scores() {
    extern __shared__ float sm[];
    float* whT = sm;             // [NH][NL]  4096 f = 16 KB
    float* wqh = sm + NH * NL;   // [NH][32]  2048 f =  8 KB (prescaled)

    const int bid = blockIdx.x;
    const int half = bid & 1;
    const int pair = bid >> 1;
    const int s = pair % NS;
    const int q = pair / NS;
    const int t = threadIdx.x;

    {
        const float4* b4 = reinterpret_cast<const float4*>(g_WhT + (size_t)s * NH * NL);
        float4* w2 = reinterpret_cast<float4*>(whT);
        for (int e = t; e < NH * NL / 4; e += 256) w2[e] = b4[e];
        const float* aq = g_WqT + (size_t)q * NH * NL + half * 32;
        for (int e = t; e < NH * 32 / 4; e += 256) {
            int h = e >> 3;
            int ii = (e & 7) * 4;
            *reinterpret_cast<float4*>(&wqh[h * 32 + ii]) =
                *reinterpret_cast<const float4*>(&aq[h * NL + ii]);
        }
    }
    __syncthreads();

    const int i0 = 2 * (t >> 4);   // local row in [0,32)
    const int j0 = 4 * (t & 15);   // col in [0,64)

    const u64 G0 = dup2(G0c), G1 = dup2(G1c), G2 = dup2(G2c), G3 = dup2(G3c),
              G4 = dup2(G4c), G5 = dup2(G5c), G6 = dup2(G6c);

    u64 accp[2][2];
    accp[0][0] = 0ull; accp[0][1] = 0ull; accp[1][0] = 0ull; accp[1][1] = 0ull;

    #pragma unroll 2
    for (int h = 0; h < NH; h++) {
        float2 a2 = *reinterpret_cast<const float2*>(&wqh[h * 32 + i0]);
        ulonglong2 b2 = *reinterpret_cast<const ulonglong2*>(&whT[h * NL + j0]);
        u64 ad[2] = {dup2(a2.x), dup2(a2.y)};
        u64 bp[2] = {b2.x, b2.y};
        #pragma unroll
        for (int r = 0; r < 2; r++) {
            #pragma unroll
            for (int cc = 0; cc < 2; cc++) {
                u64 p = f2mul(ad[r], bp[cc]);     // p = 2*log2e * x (both halves)
                float2 pf = upk(p);
                float ulo = fast_ex2(-fabsf(pf.x));
                float uhi = fast_ex2(-fabsf(pf.y));
                u64 u = pk(ulo, uhi);
                u64 g = f2fma(u, G6, G5);         // Horner: tanh(|x|)
                g = f2fma(u, g, G4);
                g = f2fma(u, g, G3);
                g = f2fma(u, g, G2);
                g = f2fma(u, g, G1);
                g = f2fma(u, g, G0);
                // sign as packed +-1.0f (one LOP3 per scalar), fold into accumulate FMA
                unsigned plo = __float_as_uint(pf.x), phi = __float_as_uint(pf.y);
                float slo = __uint_as_float((plo & 0x80000000u) | 0x3f800000u);
                float shi = __uint_as_float((phi & 0x80000000u) | 0x3f800000u);
                accp[r][cc] = f2fma(g, pk(slo, shi), accp[r][cc]);
            }
        }
    }

    // Softmax over j (rows span 16-lane groups).
    float* dstb = g_att + (size_t)((q * NS + s) * NL + half * 32 + i0) * NL + j0;
    #pragma unroll
    for (int r = 0; r < 2; r++) {
        float2 x0 = upk(accp[r][0]);
        float2 x1 = upk(accp[r][1]);
        float a0 = x0.x, a1 = x0.y, a2 = x1.x, a3 = x1.y;
        float m = fmaxf(fmaxf(a0, a1), fmaxf(a2, a3));
        #pragma unroll
        for (int d = 1; d < 16; d <<= 1)
            m = fmaxf(m, __shfl_xor_sync(0xffffffffu, m, d));
        float e0 = fast_ex2((a0 - m) * LOG2E);
        float e1 = fast_ex2((a1 - m) * LOG2E);
        float e2 = fast_ex2((a2 - m) * LOG2E);
        float e3 = fast_ex2((a3 - m) * LOG2E);
        float ssum = (e0 + e1) + (e2 + e3);
        #pragma unroll
        for (int d = 1; d < 16; d <<= 1)
            ssum += __shfl_xor_sync(0xffffffffu, ssum, d);
        float inv = fast_rcp(ssum);
        float4 v = make_float4(e0 * inv, e1 * inv, e2 * inv, e3 * inv);
        *reinterpret_cast<float4*>(dstb + (size_t)r * NL) = v;
    }
}

// K3: out[i][f] = sum_j att[i][j] * hs[j][f]. One block per (q, s, f-half).
// APAD must be a multiple of 4 so float4 reads of attT stay 16B-aligned.
#define APAD 68
__global__ __launch_bounds__(256) void k_av(const float* __restrict__ hs,
                                            float* __restrict__ out) {
    extern __shared__ float sm[];
    float* attT = sm;                 // [NL][APAD] transposed att: [j][i]
    float* hsh = sm + NL * APAD;      // [NL][128] f-half of hs[s]

    const int bid = blockIdx.x;
    const int fh = bid & 1;
    const int pair = bid >> 1;
    const int s = pair % NS;
    const int q = pair / NS;
    const int t = threadIdx.x;

    {
        const float* ag = g_att + (size_t)(q * NS + s) * NL * NL;
        for (int e = t; e < NL * NL / 4; e += 256) {
            int i = e >> 4;
            int j4 = (e & 15) * 4;
            float4 v = *reinterpret_cast<const float4*>(&ag[i * NL + j4]);
            attT[(j4 + 0) * APAD + i] = v.x;
            attT[(j4 + 1) * APAD + i] = v.y;
            attT[(j4 + 2) * APAD + i] = v.z;
            attT[(j4 + 3) * APAD + i] = v.w;
        }
        const float* hg = hs + (size_t)s * NL * NF + fh * 128;
        for (int e = t; e < NL * 128 / 4; e += 256) {
            int j = e >> 5;
            int f4 = (e & 31) * 4;
            *reinterpret_cast<float4*>(&hsh[j * 128 + f4]) =
                *reinterpret_cast<const float4*>(&hg[(size_t)j * NF + f4]);
        }
    }
    __syncthreads();

    const int i0 = 4 * (t >> 4);    // rows [0,64)
    const int fb = 8 * (t & 15);    // cols [0,128)

    u64 o[4][4];
    #pragma unroll
    for (int r = 0; r < 4; r++)
        #pragma unroll
        for (int c = 0; c < 4; c++) o[r][c] = 0ull;

    #pragma unroll 2
    for (int j = 0; j < NL; j++) {
        float4 a4 = *reinterpret_cast<const float4*>(&attT[j * APAD + i0]);
        ulonglong2 h0v = *reinterpret_cast<const ulonglong2*>(&hsh[j * 128 + fb]);
        ulonglong2 h1v = *reinterpret_cast<const ulonglong2*>(&hsh[j * 128 + fb + 4]);
        u64 d0 = dup2(a4.x), d1 = dup2(a4.y), d2 = dup2(a4.z), d3 = dup2(a4.w);
        o[0][0] = f2fma(d0, h0v.x, o[0][0]); o[0][1] = f2fma(d0, h0v.y, o[0][1]);
        o[0][2] = f2fma(d0, h1v.x, o[0][2]); o[0][3] = f2fma(d0, h1v.y, o[0][3]);
        o[1][0] = f2fma(d1, h0v.x, o[1][0]); o[1][1] = f2fma(d1, h0v.y, o[1][1]);
        o[1][2] = f2fma(d1, h1v.x, o[1][2]); o[1][3] = f2fma(d1, h1v.y, o[1][3]);
        o[2][0] = f2fma(d2, h0v.x, o[2][0]); o[2][1] = f2fma(d2, h0v.y, o[2][1]);
        o[2][2] = f2fma(d2, h1v.x, o[2][2]); o[2][3] = f2fma(d2, h1v.y, o[2][3]);
        o[3][0] = f2fma(d3, h0v.x, o[3][0]); o[3][1] = f2fma(d3, h0v.y, o[3][1]);
        o[3][2] = f2fma(d3, h1v.x, o[3][2]); o[3][3] = f2fma(d3, h1v.y, o[3][3]);
    }

    float* op = out + (size_t)((q * NS + s) * NL) * NF + fh * 128 + fb;
    #pragma unroll
    for (int r = 0; r < 4; r++) {
        ulonglong2 v0; v0.x = o[r][0]; v0.y = o[r][1];
        ulonglong2 v1; v1.x = o[r][2]; v1.y = o[r][3];
        *reinterpret_cast<ulonglong2*>(&op[(size_t)(i0 + r) * NF]) = v0;
        *reinterpret_cast<ulonglong2*>(&op[(size_t)(i0 + r) * NF + 4]) = v1;
    }
}

extern "C" void kernel_launch(void* const* d_in, const int* in_sizes, int n_in,
                              void* d_out, int out_size) {
    const float* qs = (const float*)d_in[0];
    const float* hs = (const float*)d_in[1];
    const float* W  = (const float*)d_in[2];
    const float* b  = (const float*)d_in[3];
    float* out = (float*)d_out;

    const int smem_proj = (NL * NF + NH * (NF + WPAD)) * (int)sizeof(float); // ~129 KB
    const int smem_sc   = (NH * NL + NH * 32) * (int)sizeof(float);          // 24 KB
    const int smem_av   = (NL * APAD + NL * 128) * (int)sizeof(float);       // ~49 KB
    cudaFuncSetAttribute(k_project, cudaFuncAttributeMaxDynamicSharedMemorySize, smem_proj);
    cudaFuncSetAttribute(k_scores, cudaFuncAttributeMaxDynamicSharedMemorySize, smem_sc);
    cudaFuncSetAttribute(k_av, cudaFuncAttributeMaxDynamicSharedMemorySize, smem_av);

    k_project<<<NQ + NS, 256, smem_proj>>>(qs, hs, W, b);
    k_scores<<<NQ * NS * 2, 256, smem_sc>>>();
    k_av<<<NQ * NS * 2, 256, smem_av>>>(hs, out);
}

// round 6
// speedup vs baseline: 1.2501x; 1.2501x over previous
#include <cuda_runtime.h>
#include <cstdint>

#define NQ 32
#define NS 25
#define NL 64
#define NF 256
#define NH 64

#define H_POLY 36            // poly-tanh h-range
#define ATS 68               // attT stride (mult of 4: float4-aligned)
#define XSP 260              // proj xs row stride (pad 4)

// Scratch (allocation-free rule: __device__ globals)
__device__ float g_WqT[NQ * NH * NL];  // per q: [h][i], prescaled by 2*log2e
__device__ float g_WhT[NS * NH * NL];  // per s: [h][j]

typedef unsigned long long u64;

__device__ __forceinline__ float fast_ex2(float x) {
    float r; asm("ex2.approx.f32 %0, %1;" : "=f"(r) : "f"(x)); return r;
}
__device__ __forceinline__ float fast_rcp(float x) {
    float r; asm("rcp.approx.f32 %0, %1;" : "=f"(r) : "f"(x)); return r;
}
// ---- packed f32x2 ops ----
__device__ __forceinline__ u64 f2mul(u64 a, u64 b) {
    u64 r; asm("mul.rn.f32x2 %0, %1, %2;" : "=l"(r) : "l"(a), "l"(b)); return r;
}
__device__ __forceinline__ u64 f2fma(u64 a, u64 b, u64 c) {
    u64 r; asm("fma.rn.f32x2 %0, %1, %2, %3;" : "=l"(r) : "l"(a), "l"(b), "l"(c)); return r;
}
__device__ __forceinline__ u64 pk(float lo, float hi) {
    u64 r; asm("mov.b64 %0, {%1, %2};" : "=l"(r) : "f"(lo), "f"(hi)); return r;
}
__device__ __forceinline__ float2 upk(u64 v) {
    float lo, hi; asm("mov.b64 {%0, %1}, %2;" : "=f"(lo), "=f"(hi) : "l"(v));
    return make_float2(lo, hi);
}
__device__ __forceinline__ u64 dup2(float x) { return pk(x, x); }

// Degree-6 polynomial G(u) ~= (1-u)/(1+u) on [0,1], max abs err ~3.6e-5.
#define G0c 0.999956458f
#define G1c -1.996579368f
#define G2c 1.952699598f
#define G3c -1.733862064f
#define G4c 1.203783808f
#define G5c -0.533660512f
#define G6c 0.10766208f

#define TWO_LOG2E 2.8853900817779268f   // 2*log2(e)
#define LOG2E 1.4426950408889634f

// K1: projection. One block per (sequence b, l-quarter).
// dst[h][l] = (sum_f x[l][f] * W[h][f] + bias[h]) * scale, h-major in gmem.
// W is read via L2 (broadcast: 16 lanes share each W row address).
__global__ __launch_bounds__(256) void k_project(const float* __restrict__ qs,
                                                 const float* __restrict__ hs,
                                                 const float* __restrict__ W,
                                                 const float* __restrict__ bias) {
    __shared__ float xs[16 * XSP];        // 16 rows x 256 (+pad)
    const int b  = blockIdx.x >> 2;
    const int lq = blockIdx.x & 3;
    const int t  = threadIdx.x;
    const float* x = ((b < NQ) ? (qs + (size_t)b * NL * NF)
                               : (hs + (size_t)(b - NQ) * NL * NF))
                     + (size_t)lq * 16 * NF;
    float* dst = (b < NQ) ? (g_WqT + (size_t)b * NH * NL)
                          : (g_WhT + (size_t)(b - NQ) * NH * NL);
    const float scale = (b < NQ) ? TWO_LOG2E : 1.0f;

    for (int e = t; e < 16 * NF / 4; e += 256) {
        int row = e >> 6;
        int c4 = (e & 63) * 4;
        *reinterpret_cast<float4*>(&xs[row * XSP + c4]) =
            *reinterpret_cast<const float4*>(&x[row * NF + c4]);
    }
    __syncthreads();

    const int h0 = 4 * (t >> 4);   // W loads broadcast across 16 lanes
    const int lr = t & 15;
    float acc[4] = {0.f, 0.f, 0.f, 0.f};

    #pragma unroll 2
    for (int f = 0; f < NF; f += 4) {
        float4 xv = *reinterpret_cast<const float4*>(&xs[lr * XSP + f]);
        #pragma unroll
        for (int c = 0; c < 4; c++) {
            float4 w = __ldg(reinterpret_cast<const float4*>(&W[(size_t)(h0 + c) * NF + f]));
            acc[c] = fmaf(w.x, xv.x, fmaf(w.y, xv.y, fmaf(w.z, xv.z, fmaf(w.w, xv.w, acc[c]))));
        }
    }
    const int l = lq * 16 + lr;
    #pragma unroll
    for (int c = 0; c < 4; c++)
        dst[(h0 + c) * NL + l] = (acc[c] + __ldg(&bias[h0 + c])) * scale;
}

// K2: fused scores(tanh mix) -> softmax -> att @ hs. One block per (q, s).
// smem: [0..8448) floats. Phase A: wqT[0..4096) whT[4096..8192).
// Then attT[0..4352) (stride 68) and hsq[4352..8448) overlay.
__global__ __launch_bounds__(256) void k_attn(const float* __restrict__ hs,
                                              float* __restrict__ out) {
    extern __shared__ float sm[];
    float* wqT = sm;                 // [NH][NL], prescaled by 2*log2e
    float* whT = sm + NH * NL;       // [NH][NL]
    float* attT = sm;                // overlay: [j][i], stride ATS
    float* hsq = sm + NL * ATS;      // overlay: [NL][64] f-quarter of hs[s]

    const int s = blockIdx.x;
    const int q = blockIdx.y;
    const int t = threadIdx.x;

    {
        const float4* a = reinterpret_cast<const float4*>(g_WqT + (size_t)q * NH * NL);
        const float4* b = reinterpret_cast<const float4*>(g_WhT + (size_t)s * NH * NL);
        float4* w1 = reinterpret_cast<float4*>(wqT);
        float4* w2 = reinterpret_cast<float4*>(whT);
        for (int e = t; e < NH * NL / 4; e += 256) { w1[e] = a[e]; w2[e] = b[e]; }
    }
    __syncthreads();

    const int i0 = 4 * (t >> 4);   // query rows (broadcast loads)
    const int j0 = 4 * (t & 15);   // support cols (coalesced loads)

    const u64 G0 = dup2(G0c), G1 = dup2(G1c), G2 = dup2(G2c), G3 = dup2(G3c),
              G4 = dup2(G4c), G5 = dup2(G5c), G6 = dup2(G6c);
    const u64 NEG2 = dup2(-2.0f);

    u64 accp[4][2];
    #pragma unroll
    for (int r = 0; r < 4; r++) { accp[r][0] = 0ull; accp[r][1] = 0ull; }

    // Phase A part 1: polynomial tanh (FMA-heavy, 1 MUFU/elem)
    #pragma unroll 2
    for (int h = 0; h < H_POLY; h++) {
        float4 a4 = *reinterpret_cast<const float4*>(&wqT[h * NL + i0]);
        ulonglong2 b2 = *reinterpret_cast<const ulonglong2*>(&whT[h * NL + j0]);
        u64 ad[4] = {dup2(a4.x), dup2(a4.y), dup2(a4.z), dup2(a4.w)};
        u64 bp[2] = {b2.x, b2.y};
        #pragma unroll
        for (int r = 0; r < 4; r++) {
            #pragma unroll
            for (int cc = 0; cc < 2; cc++) {
                u64 p = f2mul(ad[r], bp[cc]);     // 2*log2e * x (both halves)
                float2 pf = upk(p);
                float ulo = fast_ex2(-fabsf(pf.x));
                float uhi = fast_ex2(-fabsf(pf.y));
                u64 u = pk(ulo, uhi);
                u64 g = f2fma(u, G6, G5);
                g = f2fma(u, g, G4);
                g = f2fma(u, g, G3);
                g = f2fma(u, g, G2);
                g = f2fma(u, g, G1);
                g = f2fma(u, g, G0);              // tanh(|x|)
                unsigned plo = __float_as_uint(pf.x), phi = __float_as_uint(pf.y);
                float slo = __uint_as_float((plo & 0x80000000u) | 0x3f800000u);
                float shi = __uint_as_float((phi & 0x80000000u) | 0x3f800000u);
                accp[r][cc] = f2fma(g, pk(slo, shi), accp[r][cc]);
            }
        }
    }

    // Phase A part 2: rcp tanh = 1 - 2/(2^p + 1) (MUFU-heavy, 2.5 FMA-slot/elem).
    // Accumulate -2*r into accp; the +1-per-term constant cancels in softmax.
    #pragma unroll 2
    for (int h = H_POLY; h < NH; h++) {
        float4 a4 = *reinterpret_cast<const float4*>(&wqT[h * NL + i0]);
        ulonglong2 b2 = *reinterpret_cast<const ulonglong2*>(&whT[h * NL + j0]);
        u64 ad[4] = {dup2(a4.x), dup2(a4.y), dup2(a4.z), dup2(a4.w)};
        u64 bp[2] = {b2.x, b2.y};
        #pragma unroll
        for (int r = 0; r < 4; r++) {
            #pragma unroll
            for (int cc = 0; cc < 2; cc++) {
                u64 p = f2mul(ad[r], bp[cc]);
                float2 pf = upk(p);
                float e0 = fast_ex2(pf.x);        // 2^p; inf-safe (rcp(inf)=0)
                float e1 = fast_ex2(pf.y);
                float r0 = fast_rcp(e0 + 1.0f);
                float r1 = fast_rcp(e1 + 1.0f);
                accp[r][cc] = f2fma(pk(r0, r1), NEG2, accp[r][cc]);
            }
        }
    }

    // Phase B: softmax over j per row (rows span 16-lane groups).
    float accs[4][4], inv[4];
    #pragma unroll
    for (int r = 0; r < 4; r++) {
        float2 x0 = upk(accp[r][0]);
        float2 x1 = upk(accp[r][1]);
        accs[r][0] = x0.x; accs[r][1] = x0.y; accs[r][2] = x1.x; accs[r][3] = x1.y;
        float m = fmaxf(fmaxf(accs[r][0], accs[r][1]), fmaxf(accs[r][2], accs[r][3]));
        #pragma unroll
        for (int d = 1; d < 16; d <<= 1)
            m = fmaxf(m, __shfl_xor_sync(0xffffffffu, m, d));
        float e0 = fast_ex2((accs[r][0] - m) * LOG2E);
        float e1 = fast_ex2((accs[r][1] - m) * LOG2E);
        float e2 = fast_ex2((accs[r][2] - m) * LOG2E);
        float e3 = fast_ex2((accs[r][3] - m) * LOG2E);
        accs[r][0] = e0; accs[r][1] = e1; accs[r][2] = e2; accs[r][3] = e3;
        float ssum = (e0 + e1) + (e2 + e3);
        #pragma unroll
        for (int d = 1; d < 16; d <<= 1)
            ssum += __shfl_xor_sync(0xffffffffu, ssum, d);
        inv[r] = fast_rcp(ssum);
    }

    __syncthreads();  // all phase-A smem reads complete before overlay writes

    // Store att transposed: attT[j][i], float4 over i (one STS.128 per c).
    #pragma unroll
    for (int c = 0; c < 4; c++) {
        float4 v = make_float4(accs[0][c] * inv[0], accs[1][c] * inv[1],
                               accs[2][c] * inv[2], accs[3][c] * inv[3]);
        *reinterpret_cast<float4*>(&attT[(j0 + c) * ATS + i0]) = v;
    }

    // Phase C: out[i][f] = sum_j att[i][j] * hs[j][f], 4 f-quarter passes.
    const float* hg = hs + (size_t)s * NL * NF;
    float* op = out + (size_t)((q * NS + s) * NL) * NF;
    const int fb = 4 * (t & 15);

    #pragma unroll
    for (int p = 0; p < 4; p++) {
        // stage hs[s][:, 64p .. 64p+64) into hsq
        for (int e = t; e < NL * 64 / 4; e += 256) {
            int j = e >> 4;
            int f4 = (e & 15) * 4;
            *reinterpret_cast<float4*>(&hsq[j * 64 + f4]) =
                __ldg(reinterpret_cast<const float4*>(&hg[(size_t)j * NF + 64 * p + f4]));
        }
        __syncthreads();   // attT store (p==0) + hsq ready

        u64 o[4][2];
        #pragma unroll
        for (int r = 0; r < 4; r++) { o[r][0] = 0ull; o[r][1] = 0ull; }

        #pragma unroll 4
        for (int j = 0; j < NL; j++) {
            float4 a4 = *reinterpret_cast<const float4*>(&attT[j * ATS + i0]);
            ulonglong2 hv = *reinterpret_cast<const ulonglong2*>(&hsq[j * 64 + fb]);
            u64 d0 = dup2(a4.x), d1 = dup2(a4.y), d2 = dup2(a4.z), d3 = dup2(a4.w);
            o[0][0] = f2fma(d0, hv.x, o[0][0]); o[0][1] = f2fma(d0, hv.y, o[0][1]);
            o[1][0] = f2fma(d1, hv.x, o[1][0]); o[1][1] = f2fma(d1, hv.y, o[1][1]);
            o[2][0] = f2fma(d2, hv.x, o[2][0]); o[2][1] = f2fma(d2, hv.y, o[2][1]);
            o[3][0] = f2fma(d3, hv.x, o[3][0]); o[3][1] = f2fma(d3, hv.y, o[3][1]);
        }
        #pragma unroll
        for (int r = 0; r < 4; r++) {
            ulonglong2 v; v.x = o[r][0]; v.y = o[r][1];
            *reinterpret_cast<ulonglong2*>(&op[(size_t)(i0 + r) * NF + 64 * p + fb]) = v;
        }
        __syncthreads();   // compute reads done before next hsq overwrite
    }
}

extern "C" void kernel_launch(void* const* d_in, const int* in_sizes, int n_in,
                              void* d_out, int out_size) {
    const float* qs = (const float*)d_in[0];
    const float* hs = (const float*)d_in[1];
    const float* W  = (const float*)d_in[2];
    const float* b  = (const float*)d_in[3];
    float* out = (float*)d_out;

    const int smem_attn = (NL * ATS + NL * 64) * (int)sizeof(float);  // 33792 B
    cudaFuncSetAttribute(k_attn, cudaFuncAttributeMaxDynamicSharedMemorySize, smem_attn);

    k_project<<<(NQ + NS) * 4, 256>>>(qs, hs, W, b);
    k_attn<<<dim3(NS, NQ), 256, smem_attn>>>(hs, out);
}

// round 7
// speedup vs baseline: 1.7993x; 1.4393x over previous
#include <cuda_runtime.h>
#include <cstdint>

#define NQ 32
#define NS 25
#define NL 64
#define NF 256
#define NH 64

#define ATS2 34     // attT2 row stride in float2 units (2-way-conflict store, aligned reads)
#define XSP 260     // proj xs row stride (pad 4)

// Scratch (allocation-free rule: __device__ globals)
__device__ float g_WqT[NQ * NH * NL];  // per q: [h][i]
__device__ float g_WhT[NS * NH * NL];  // per s: [h][j]

typedef unsigned long long u64;

__device__ __forceinline__ float fast_ex2(float x) {
    float r; asm("ex2.approx.f32 %0, %1;" : "=f"(r) : "f"(x)); return r;
}
__device__ __forceinline__ float fast_rcp(float x) {
    float r; asm("rcp.approx.f32 %0, %1;" : "=f"(r) : "f"(x)); return r;
}
__device__ __forceinline__ float fast_tanh(float x) {
    float r; asm("tanh.approx.f32 %0, %1;" : "=f"(r) : "f"(x)); return r;
}
__device__ __forceinline__ u64 f2fma(u64 a, u64 b, u64 c) {
    u64 r; asm("fma.rn.f32x2 %0, %1, %2, %3;" : "=l"(r) : "l"(a), "l"(b), "l"(c)); return r;
}

#define LOG2E 1.4426950408889634f

// K1: projection. One block per (sequence b, l-quarter).
// dst[h][l] = sum_f x[l][f] * W[h][f] + bias[h], h-major in gmem.
__global__ __launch_bounds__(256) void k_project(const float* __restrict__ qs,
                                                 const float* __restrict__ hs,
                                                 const float* __restrict__ W,
                                                 const float* __restrict__ bias) {
    __shared__ float xs[16 * XSP];        // 16 rows x 256 (+pad)
    const int b  = blockIdx.x >> 2;
    const int lq = blockIdx.x & 3;
    const int t  = threadIdx.x;
    const float* x = ((b < NQ) ? (qs + (size_t)b * NL * NF)
                               : (hs + (size_t)(b - NQ) * NL * NF))
                     + (size_t)lq * 16 * NF;
    float* dst = (b < NQ) ? (g_WqT + (size_t)b * NH * NL)
                          : (g_WhT + (size_t)(b - NQ) * NH * NL);

    for (int e = t; e < 16 * NF / 4; e += 256) {
        int row = e >> 6;
        int c4 = (e & 63) * 4;
        *reinterpret_cast<float4*>(&xs[row * XSP + c4]) =
            *reinterpret_cast<const float4*>(&x[row * NF + c4]);
    }
    __syncthreads();

    const int h0 = 4 * (t >> 4);   // W loads broadcast across 16 lanes
    const int lr = t & 15;
    float acc[4] = {0.f, 0.f, 0.f, 0.f};

    #pragma unroll 2
    for (int f = 0; f < NF; f += 4) {
        float4 xv = *reinterpret_cast<const float4*>(&xs[lr * XSP + f]);
        #pragma unroll
        for (int c = 0; c < 4; c++) {
            float4 w = __ldg(reinterpret_cast<const float4*>(&W[(size_t)(h0 + c) * NF + f]));
            acc[c] = fmaf(w.x, xv.x, fmaf(w.y, xv.y, fmaf(w.z, xv.z, fmaf(w.w, xv.w, acc[c]))));
        }
    }
    const int l = lq * 16 + lr;
    #pragma unroll
    for (int c = 0; c < 4; c++)
        dst[(h0 + c) * NL + l] = acc[c] + __ldg(&bias[h0 + c]);
}

// K2: fused scores(tanh) -> softmax -> att @ hs. One block per (q, s, i-half).
// smem layout (floats):
//   phase A: wqh [0..2048)  = [NH][32];  whT [2048..6144) = [NH][64]
//   overlay: attT2 [0..4352) = [NL][ATS2] float2 (duplicated pairs)
//            hsq  [4352..12544) = [NL][128] f-half of hs[s]
// total 12544 floats = 50176 B  -> occupancy 4 blocks/SM (pinned; 1600/592 = 2.7 -> 3 even waves)
__global__ __launch_bounds__(256) void k_attn(const float* __restrict__ hs,
                                              float* __restrict__ out) {
    extern __shared__ float sm[];
    float* wqh = sm;                                   // [NH][32]
    float* whT = sm + 2048;                            // [NH][64]
    float2* attT2 = reinterpret_cast<float2*>(sm);     // [NL][ATS2]
    float* hsq = sm + 4352;                            // [NL][128]

    const int sb = blockIdx.x;
    const int s = sb >> 1;
    const int half = sb & 1;
    const int q = blockIdx.y;
    const int t = threadIdx.x;

    {
        const float4* bsrc = reinterpret_cast<const float4*>(g_WhT + (size_t)s * NH * NL);
        float4* w2 = reinterpret_cast<float4*>(whT);
        for (int e = t; e < NH * NL / 4; e += 256) w2[e] = bsrc[e];
        const float* aq = g_WqT + (size_t)q * NH * NL + half * 32;
        for (int e = t; e < NH * 32 / 4; e += 256) {
            int h = e >> 3;
            int ii = (e & 7) * 4;
            *reinterpret_cast<float4*>(&wqh[h * 32 + ii]) =
                *reinterpret_cast<const float4*>(&aq[h * NL + ii]);
        }
    }
    __syncthreads();

    const int i0a = 2 * (t >> 4);   // local query row in [0,32) (broadcast loads)
    const int j0 = 4 * (t & 15);    // support col in [0,64) (coalesced loads)

    // Phase A: acc[r][c] = sum_h tanh(wq[i0a+r][h] * wh[j0+c][h])
    float acc[2][4];
    #pragma unroll
    for (int r = 0; r < 2; r++)
        #pragma unroll
        for (int c = 0; c < 4; c++) acc[r][c] = 0.f;

    #pragma unroll 4
    for (int h = 0; h < NH; h++) {
        float2 a2 = *reinterpret_cast<const float2*>(&wqh[h * 32 + i0a]);
        float4 b4 = *reinterpret_cast<const float4*>(&whT[h * NL + j0]);
        acc[0][0] += fast_tanh(a2.x * b4.x);
        acc[0][1] += fast_tanh(a2.x * b4.y);
        acc[0][2] += fast_tanh(a2.x * b4.z);
        acc[0][3] += fast_tanh(a2.x * b4.w);
        acc[1][0] += fast_tanh(a2.y * b4.x);
        acc[1][1] += fast_tanh(a2.y * b4.y);
        acc[1][2] += fast_tanh(a2.y * b4.z);
        acc[1][3] += fast_tanh(a2.y * b4.w);
    }

    // Phase B: softmax over j per row (each row's 64 j live in a 16-lane group).
    float inv[2];
    #pragma unroll
    for (int r = 0; r < 2; r++) {
        float m = fmaxf(fmaxf(acc[r][0], acc[r][1]), fmaxf(acc[r][2], acc[r][3]));
        #pragma unroll
        for (int d = 1; d < 16; d <<= 1)
            m = fmaxf(m, __shfl_xor_sync(0xffffffffu, m, d));
        float e0 = fast_ex2((acc[r][0] - m) * LOG2E);
        float e1 = fast_ex2((acc[r][1] - m) * LOG2E);
        float e2 = fast_ex2((acc[r][2] - m) * LOG2E);
        float e3 = fast_ex2((acc[r][3] - m) * LOG2E);
        acc[r][0] = e0; acc[r][1] = e1; acc[r][2] = e2; acc[r][3] = e3;
        float ssum = (e0 + e1) + (e2 + e3);
        #pragma unroll
        for (int d = 1; d < 16; d <<= 1)
            ssum += __shfl_xor_sync(0xffffffffu, ssum, d);
        inv[r] = fast_rcp(ssum);
    }

    __syncthreads();  // all phase-A smem reads done before overlay writes

    // Store att transposed + duplicated: attT2[j][i] = (v, v)
    #pragma unroll
    for (int c = 0; c < 4; c++) {
        #pragma unroll
        for (int r = 0; r < 2; r++) {
            float v = acc[r][c] * inv[r];
            attT2[(j0 + c) * ATS2 + (i0a + r)] = make_float2(v, v);
        }
    }

    // Phase C: out[i][f] = sum_j att[i][j] * hs[j][f], 2 f-half passes.
    const float* hg = hs + (size_t)s * NL * NF;
    float* op = out + (size_t)((q * NS + s) * NL + half * 32) * NF;
    const int i0c = 4 * (t >> 5);   // warp-uniform: att loads broadcast
    const int fb = 4 * (t & 31);    // [0,128)

    #pragma unroll
    for (int p = 0; p < 2; p++) {
        for (int e = t; e < NL * 128 / 4; e += 256) {
            int j = e >> 5;
            int f4 = (e & 31) * 4;
            *reinterpret_cast<float4*>(&hsq[j * 128 + f4]) =
                __ldg(reinterpret_cast<const float4*>(&hg[(size_t)j * NF + 128 * p + f4]));
        }
        __syncthreads();   // attT2 stores (p==0) + hsq staged

        u64 o[4][2];
        #pragma unroll
        for (int r = 0; r < 4; r++) { o[r][0] = 0ull; o[r][1] = 0ull; }

        #pragma unroll 4
        for (int j = 0; j < NL; j++) {
            ulonglong2 a01 = *reinterpret_cast<const ulonglong2*>(&attT2[j * ATS2 + i0c]);
            ulonglong2 a23 = *reinterpret_cast<const ulonglong2*>(&attT2[j * ATS2 + i0c + 2]);
            ulonglong2 hv = *reinterpret_cast<const ulonglong2*>(&hsq[j * 128 + fb]);
            o[0][0] = f2fma(a01.x, hv.x, o[0][0]); o[0][1] = f2fma(a01.x, hv.y, o[0][1]);
            o[1][0] = f2fma(a01.y, hv.x, o[1][0]); o[1][1] = f2fma(a01.y, hv.y, o[1][1]);
            o[2][0] = f2fma(a23.x, hv.x, o[2][0]); o[2][1] = f2fma(a23.x, hv.y, o[2][1]);
            o[3][0] = f2fma(a23.y, hv.x, o[3][0]); o[3][1] = f2fma(a23.y, hv.y, o[3][1]);
        }
        #pragma unroll
        for (int r = 0; r < 4; r++) {
            ulonglong2 v; v.x = o[r][0]; v.y = o[r][1];
            *reinterpret_cast<ulonglong2*>(&op[(size_t)(i0c + r) * NF + 128 * p + fb]) = v;
        }
        __syncthreads();   // reads done before next hsq overwrite
    }
}

extern "C" void kernel_launch(void* const* d_in, const int* in_sizes, int n_in,
                              void* d_out, int out_size) {
    const float* qs = (const float*)d_in[0];
    const float* hs = (const float*)d_in[1];
    const float* W  = (const float*)d_in[2];
    const float* b  = (const float*)d_in[3];
    float* out = (float*)d_out;

    const int smem_attn = 12544 * (int)sizeof(float);  // 50176 B -> occ 4
    cudaFuncSetAttribute(k_attn, cudaFuncAttributeMaxDynamicSharedMemorySize, smem_attn);

    k_project<<<(NQ + NS) * 4, 256>>>(qs, hs, W, b);
    k_attn<<<dim3(2 * NS, NQ), 256, smem_attn>>>(hs, out);
}